// round 16
// baseline (speedup 1.0000x reference)
#include <cuda_runtime.h>
#include <math.h>

#define BB   1024
#define NN   50
#define NP1  51
#define DD   128
#define KK   8
#define EPS  1e-5f
#define ADJS 68                          // adjT row stride: gcd(68,32)=4 -> 4-way conflicts
#define GSP  1344                        // gather split: warps 0-3 take [0,1344), 4-7 take [1344,1600)

typedef unsigned long long ull;

// ---- scratch (device globals) ----
__device__ float  g_y1[(size_t)BB * NP1 * DD];
__device__ float  g_y2[(size_t)BB * DD];
__device__ float  g_mean[NP1];
__device__ float  g_istd[NP1];
__device__ float  g_s1[(size_t)NP1 * BB];
__device__ float  g_s2[(size_t)NP1 * BB];
__device__ float  g_p2s[BB];
__device__ float  g_p2q[BB];
__device__ float4 g_Wp4[32 * 128];               // gcn_W packed [j4][d]
__device__ float4 g_Ap4[32 * 128];               // att_W packed [j4][d]

// ---- packed f32x2 helpers ----
#define FMA2(acc, a, b) asm("fma.rn.f32x2 %0, %1, %2, %0;" : "+l"(acc) : "l"(a), "l"(b))
__device__ __forceinline__ float2 unpk(ull v) {
    float2 r; asm("mov.b64 {%0,%1}, %2;" : "=f"(r.x), "=f"(r.y) : "l"(v)); return r;
}
__device__ __forceinline__ ull pk(float x, float y) {
    ull r; asm("mov.b64 %0, {%1,%2};" : "=l"(r) : "f"(x), "f"(y)); return r;
}

// ---- K1 smem layout (float offsets; vector regions 16B-aligned) ----
#define SM_X     0                       // [56][128]  x, later reused for xo
#define SM_ADJT  7168                    // [51][68]   adjT padded, i pad 51..67 = 0
#define SM_Q     10640                   // 128
#define SM_P     10768                   // 128
#define SM_ATT   10896                   // 64
#define SM_C     10960                   // 8
#define SM_RED   10968                   // 256
#define SM_NEB   11224                   // 52 ints
#define SM_NEBR  11276                   // 400 ints
#define SMEM_K1_FLOATS 11676
#define SMEM_K1_BYTES  (SMEM_K1_FLOATS * 4)   // ~45.6 KB

// k0: pack weight matrices into [j4][d] float4 layout
__global__ void k0(const float* __restrict__ att_W, const float* __restrict__ gcn_W)
{
    int idx = blockIdx.x * blockDim.x + threadIdx.x;
    if (idx < 32 * 128) {
        int j4 = idx >> 7, d = idx & 127;
        g_Wp4[idx] = *(const float4*)(gcn_W + (size_t)d * DD + 4 * j4);
        g_Ap4[idx] = *(const float4*)(att_W + (size_t)d * DD + 4 * j4);
    }
}

__device__ __forceinline__ void gather_body(
    float* s_x, const int* s_neb, const int* s_nebr,
    const float4* ent4, const float4* rel4, int t)
{
    int n = t >> 5, c = t & 31;
    float4 e = ent4[(size_t)s_neb[n]*32 + c];
    const int* nr = s_nebr + n*KK;
    float4 rm = make_float4(0.f,0.f,0.f,0.f);
    #pragma unroll
    for (int k = 0; k < KK; k++) {
        float4 rv = rel4[(size_t)nr[k]*32 + c];
        rm.x += rv.x; rm.y += rv.y; rm.z += rv.z; rm.w += rv.w;
    }
    float4 o;
    o.x = 0.5f*(e.x + rm.x*0.125f);
    o.y = 0.5f*(e.y + rm.y*0.125f);
    o.z = 0.5f*(e.z + rm.z*0.125f);
    o.w = 0.5f*(e.w + rm.w*0.125f);
    *(float4*)(s_x + (n+1)*DD + 4*c) = o;
}

__global__ __launch_bounds__(256, 2) void k1(
    const int* __restrict__ hrt, const int* __restrict__ neb,
    const int* __restrict__ nebr, const float* __restrict__ adj,
    const float* __restrict__ ent_W, const float* __restrict__ rel_W,
    const float* __restrict__ att_W, const float* __restrict__ att_b,
    const float* __restrict__ gcn_b,
    float* __restrict__ out)
{
    extern __shared__ float sm[];
    const int b = blockIdx.x, tid = threadIdx.x;
    float* s_x    = sm + SM_X;
    float* s_adjT = sm + SM_ADJT;
    float* s_q    = sm + SM_Q;
    float* s_p    = sm + SM_P;
    float* s_att  = sm + SM_ATT;
    float* s_c    = sm + SM_C;
    float* s_red  = sm + SM_RED;
    int*   s_neb  = (int*)(sm + SM_NEB);
    int*   s_nebr = (int*)(sm + SM_NEBR);

    // ---- phase 1 (all threads): indices, sum_hrt, phantom-row zero (NO adjT) ----
    if (tid < DD) {
        int hi = hrt[3*b+0], ri = hrt[3*b+1], ti = hrt[3*b+2];
        float h = ent_W[(size_t)hi*DD + tid];
        float t = ent_W[(size_t)ti*DD + tid];
        float r = rel_W[(size_t)ri*DD + tid];
        out[(size_t)0*BB*DD + (size_t)b*DD + tid] = h;
        out[(size_t)1*BB*DD + (size_t)b*DD + tid] = t;
        out[(size_t)2*BB*DD + (size_t)b*DD + tid] = r;
        s_x[tid] = (h + t + r) * (1.0f/3.0f);
    }
    for (int t = tid; t < NN; t += 256) s_neb[t] = neb[b*NN + t];
    for (int t = tid; t < NN*KK; t += 256) s_nebr[t] = nebr[(size_t)b*NN*KK + t];
    // zero phantom rows 51..55 of s_x
    for (int idx = tid; idx < 5*DD; idx += 256) s_x[NP1*DD + idx] = 0.0f;
    __syncthreads();

    // ---- phase 2: warp-specialized ----
    const float4* ent4 = (const float4*)ent_W;
    const float4* rel4 = (const float4*)rel_W;
    if (tid < 128) {
        // warps 0-3: gather items [0, GSP)
        for (int t = tid; t < GSP; t += 128)
            gather_body(s_x, s_neb, s_nebr, ent4, rel4, t);
    } else {
        // warps 4-7: (c) q[d] + c-partials; (d) p[j]; adjT; then gather tail
        const int d = tid - 128;
        {
            ull acc = 0;
            const ulonglong2* Ap = (const ulonglong2*)g_Ap4;
            #pragma unroll 8
            for (int j4 = 0; j4 < 32; j4++) {
                ulonglong2 w = Ap[j4*128 + d];
                ulonglong2 x = *(const ulonglong2*)(s_x + 4*j4);   // row 0 (phase 1)
                FMA2(acc, x.x, w.x);
                FMA2(acc, x.y, w.y);
            }
            float2 f = unpk(acc);
            float ab = att_b[d];
            float qv = f.x + f.y + ab;
            s_q[d] = qv;
            float cv = qv * ab;
            #pragma unroll
            for (int o = 16; o; o >>= 1) cv += __shfl_xor_sync(0xffffffffu, cv, o);
            if ((d & 31) == 0) s_c[1 + (d >> 5)] = cv;
        }
        asm volatile("bar.sync 1, 128;" ::: "memory");   // warps 4-7 only
        {
            float acc = 0.0f;
            #pragma unroll 8
            for (int dd = 0; dd < DD; dd++) acc = fmaf(s_q[dd], att_W[(size_t)dd*DD + d], acc);
            s_p[d] = acc;
            if (d == 0) s_c[0] = s_c[1] + s_c[2] + s_c[3] + s_c[4];
        }
        // adjT pad-zero + transpose (hidden under gather)
        for (int idx = d; idx < NP1*17; idx += 128) {
            int j = idx / 17, i = idx % 17;
            s_adjT[j*ADJS + NP1 + i] = 0.0f;
        }
        for (int idx = d; idx < NP1*NP1; idx += 128) {
            int i = idx / NP1, j = idx % NP1;
            s_adjT[j*ADJS + i] = adj[(size_t)b*NP1*NP1 + idx];
        }
        // gather tail [GSP, 1600): exactly 2 iterations, rows n>=42 (disjoint from warps 0-3)
        for (int t = GSP + d; t < NN*32; t += 128)
            gather_body(s_x, s_neb, s_nebr, ent4, rel4, t);
    }
    __syncthreads();

    // (e) att[n] = leaky_relu( subg_n . p + c )
    {
        int warp = tid >> 5, lane = tid & 31;
        float c = s_c[0];
        for (int n = warp; n < NN; n += 8) {
            const float* row = s_x + (n+1)*DD;
            float v = 0.0f;
            #pragma unroll
            for (int k = 0; k < 4; k++) { int j = lane + 32*k; v = fmaf(row[j], s_p[j], v); }
            #pragma unroll
            for (int o = 16; o; o >>= 1) v += __shfl_xor_sync(0xffffffffu, v, o);
            if (lane == 0) {
                float a = v + c;
                s_att[n] = (a >= 0.0f) ? a : 0.01f*a;
            }
        }
    }
    __syncthreads();

    // (f) softmax over 50 (warp 0)
    if (tid < 32) {
        float v0 = (tid       < NN) ? s_att[tid]      : -3.4e38f;
        float v1 = (tid + 32  < NN) ? s_att[tid + 32] : -3.4e38f;
        float m = fmaxf(v0, v1);
        #pragma unroll
        for (int o = 16; o; o >>= 1) m = fmaxf(m, __shfl_xor_sync(0xffffffffu, m, o));
        float e0 = (tid      < NN) ? expf(v0 - m) : 0.0f;
        float e1 = (tid + 32 < NN) ? expf(v1 - m) : 0.0f;
        float s = e0 + e1;
        #pragma unroll
        for (int o = 16; o; o >>= 1) s += __shfl_xor_sync(0xffffffffu, s, o);
        float inv = 1.0f / s;
        if (tid      < NN) s_att[tid]      = e0*inv;
        if (tid + 32 < NN) s_att[tid + 32] = e1*inv;
    }
    __syncthreads();

    // (g) scale rows 1..50 in place
    for (int idx = tid; idx < NN*DD; idx += 256) s_x[DD + idx] *= s_att[idx >> 7];
    __syncthreads();

    // (h) xo[i][d] = gcn_b[d] + sum_j x[i][j]*gcn_W[d][j]
    // 2 d-cols x 14 rows per thread; results in regs, written back into s_x
    {
        const int d2 = tid & 63, rg = tid >> 6, i0 = rg * 14;
        ull acc[14][2];
        #pragma unroll
        for (int r = 0; r < 14; r++) { acc[r][0] = 0ULL; acc[r][1] = 0ULL; }
        const ulonglong2* Wp = (const ulonglong2*)g_Wp4;
        for (int j4 = 0; j4 < 32; j4++) {
            ulonglong2 w0 = Wp[j4*128 + 2*d2];
            ulonglong2 w1 = Wp[j4*128 + 2*d2 + 1];
            #pragma unroll
            for (int r = 0; r < 14; r++) {
                ulonglong2 xv = *(const ulonglong2*)(s_x + (i0+r)*DD + 4*j4);  // broadcast
                FMA2(acc[r][0], xv.x, w0.x); FMA2(acc[r][0], xv.y, w0.y);
                FMA2(acc[r][1], xv.x, w1.x); FMA2(acc[r][1], xv.y, w1.y);
            }
        }
        __syncthreads();   // all reads of s_x complete before overwrite
        float b0 = gcn_b[2*d2], b1 = gcn_b[2*d2+1];
        #pragma unroll
        for (int r = 0; r < 14; r++) {
            float2 f0 = unpk(acc[r][0]);
            float2 f1 = unpk(acc[r][1]);
            *(float2*)(s_x + (i0+r)*DD + 2*d2) =
                make_float2(f0.x + f0.y + b0, f1.x + f1.y + b1);
        }
    }
    __syncthreads();

    // (j) y1[i][d] = relu( sum_j adj[i][j]*xo[j][d] )   (xo lives in s_x)
    {
        const int d2 = tid & 63, rg = tid >> 6, i0 = rg * 16;
        const int lane = tid & 31, wh = (tid >> 5) & 1;
        ull acc[8][2];
        #pragma unroll
        for (int m = 0; m < 8; m++) { acc[m][0] = 0ULL; acc[m][1] = 0ULL; }
        for (int j = 0; j < NP1; j++) {
            float2 xf = *(const float2*)(s_x + j*DD + 2*d2);
            ull x0 = pk(xf.x, xf.x), x1 = pk(xf.y, xf.y);
            const ulonglong2* ar = (const ulonglong2*)(s_adjT + j*ADJS + i0);  // broadcast
            #pragma unroll
            for (int q = 0; q < 4; q++) {
                ulonglong2 av = ar[q];
                FMA2(acc[2*q  ][0], av.x, x0); FMA2(acc[2*q  ][1], av.x, x1);
                FMA2(acc[2*q+1][0], av.y, x0); FMA2(acc[2*q+1][1], av.y, x1);
            }
        }
        #pragma unroll
        for (int m = 0; m < 8; m++) {
            float2 f0 = unpk(acc[m][0]);
            float2 f1 = unpk(acc[m][1]);
            float v00 = fmaxf(f0.x, 0.f), v01 = fmaxf(f1.x, 0.f);
            float v10 = fmaxf(f0.y, 0.f), v11 = fmaxf(f1.y, 0.f);
            int r0 = i0 + 2*m, r1 = r0 + 1;
            if (r0 < NP1) *(float2*)(g_y1 + ((size_t)b*NP1 + r0)*DD + 2*d2) = make_float2(v00, v01);
            if (r1 < NP1) *(float2*)(g_y1 + ((size_t)b*NP1 + r1)*DD + 2*d2) = make_float2(v10, v11);
            float sv0 = v00 + v01, sq0 = v00*v00 + v01*v01;
            float sv1 = v10 + v11, sq1 = v10*v10 + v11*v11;
            #pragma unroll
            for (int o = 16; o; o >>= 1) {
                sv0 += __shfl_xor_sync(0xffffffffu, sv0, o);
                sq0 += __shfl_xor_sync(0xffffffffu, sq0, o);
                sv1 += __shfl_xor_sync(0xffffffffu, sv1, o);
                sq1 += __shfl_xor_sync(0xffffffffu, sq1, o);
            }
            if (lane == 0) {
                if (r0 < NP1) { s_red[r0*2 + wh] = sv0; s_red[128 + r0*2 + wh] = sq0; }
                if (r1 < NP1) { s_red[r1*2 + wh] = sv1; s_red[128 + r1*2 + wh] = sq1; }
            }
        }
    }
    __syncthreads();
    if (tid < NP1) {
        g_s1[(size_t)tid*BB + b] = s_red[tid*2] + s_red[tid*2+1];
        g_s2[(size_t)tid*BB + b] = s_red[128 + tid*2] + s_red[128 + tid*2+1];
    }
}

// k2: reduce partials -> mean/istd  (fp32 fixed-order tree, fp64 finalize)
__global__ void k2(void)
{
    const int i = blockIdx.x, tid = threadIdx.x;
    float s = 0.0f, s2 = 0.0f;
    #pragma unroll
    for (int t = tid; t < BB; t += 256) {
        s  += g_s1[(size_t)i*BB + t];
        s2 += g_s2[(size_t)i*BB + t];
    }
    __shared__ float rs[256], rq[256];
    rs[tid] = s; rq[tid] = s2;
    __syncthreads();
    for (int o = 128; o; o >>= 1) {
        if (tid < o) { rs[tid] += rs[tid+o]; rq[tid] += rq[tid+o]; }
        __syncthreads();
    }
    if (tid == 0) {
        double cnt = (double)BB * DD;
        double m = (double)rs[0]/cnt;
        double var = (double)rq[0]/cnt - m*m;
        g_mean[i] = (float)m;
        g_istd[i] = (float)(1.0/sqrt(var + (double)EPS));
    }
}

// k3: y2 = relu( sum_j (a_j*sc_j)*y1_j + sum_j a_j*sh_j )  — BN folded
// 2 batches per CTA (grid 512); 4 j-groups x 13 prefetched loads per thread (MLP 13)
__global__ __launch_bounds__(256) void k3(
    const float* __restrict__ adj,
    const float* __restrict__ bn_gamma, const float* __restrict__ bn_beta)
{
    __shared__ float4 s_part4[2][4 * 32];
    __shared__ float s_w[2][64];         // padded; rows 51..63 weight 0
    __shared__ float s_c0p[2][64];
    __shared__ float s_c0[2];
    __shared__ float s_r[2][8];
    const int tid = threadIdx.x;
    const int half = tid >> 7, t2 = tid & 127;
    const int b = blockIdx.x * 2 + half;
    if (t2 < 64) { s_w[half][t2] = 0.0f; s_c0p[half][t2] = 0.0f; }
    __syncthreads();
    if (t2 < NP1) {
        float a  = adj[(size_t)b*NP1*NP1 + t2];      // adj row 0
        float sc = g_istd[t2] * bn_gamma[t2];
        float sh = bn_beta[t2] - g_mean[t2]*sc;
        s_w[half][t2]   = a * sc;
        s_c0p[half][t2] = a * sh;
    }
    __syncthreads();
    {
        const int d4 = t2 & 31, jg = t2 >> 5;        // jg in 0..3
        const float* ybase = g_y1 + (size_t)b*NP1*DD + 4*d4;
        float4 v[13];
        float  w[13];
        #pragma unroll
        for (int t = 0; t < 13; t++) {
            int j = jg + 4*t;                        // 0..51
            int jc = (j < NP1) ? j : NP1 - 1;        // clamp addr; weight 0 if OOB
            w[t] = s_w[half][(j < 64) ? j : 63];
            if (j >= NP1) w[t] = 0.0f;
            v[t] = *(const float4*)(ybase + (size_t)jc*DD);
        }
        float4 acc = make_float4(0.f,0.f,0.f,0.f);
        #pragma unroll
        for (int t = 0; t < 13; t++) {
            acc.x = fmaf(w[t], v[t].x, acc.x); acc.y = fmaf(w[t], v[t].y, acc.y);
            acc.z = fmaf(w[t], v[t].z, acc.z); acc.w = fmaf(w[t], v[t].w, acc.w);
        }
        s_part4[half][jg*32 + d4] = acc;
    }
    if (t2 < 32) {   // warp 0 (half 0) and warp 4 (half 1)
        float v = s_c0p[half][t2] + s_c0p[half][t2 + 32];   // zero-padded beyond 51
        #pragma unroll
        for (int o = 16; o; o >>= 1) v += __shfl_xor_sync(0xffffffffu, v, o);
        if (t2 == 0) s_c0[half] = v;
    }
    __syncthreads();
    {
        const float* s_part = (const float*)s_part4[half];
        float v = s_c0[half];
        #pragma unroll
        for (int g = 0; g < 4; g++) v += s_part[g*DD + t2];
        v = fmaxf(v, 0.f);
        g_y2[(size_t)b*DD + t2] = v;
        float sv = v, sq = v*v;
        #pragma unroll
        for (int o = 16; o; o >>= 1) {
            sv += __shfl_xor_sync(0xffffffffu, sv, o);
            sq += __shfl_xor_sync(0xffffffffu, sq, o);
        }
        if ((t2 & 31) == 0) { s_r[half][t2>>5] = sv; s_r[half][4 + (t2>>5)] = sq; }
    }
    __syncthreads();
    if (t2 == 0) {
        g_p2s[b] = s_r[half][0] + s_r[half][1] + s_r[half][2] + s_r[half][3];
        g_p2q[b] = s_r[half][4] + s_r[half][5] + s_r[half][6] + s_r[half][7];
    }
}

// k5: redundant deterministic reduce of BN2 partials (fp32 tree, fp64 finalize) + affine
__global__ __launch_bounds__(256) void k5(
    const float* __restrict__ bn_gamma, const float* __restrict__ bn_beta,
    float* __restrict__ out)
{
    __shared__ float rs[256], rq[256];
    __shared__ float s_ms[2];
    const int tid = threadIdx.x;
    float s = 0.0f, q = 0.0f;
    #pragma unroll
    for (int t = tid; t < BB; t += 256) {
        s += g_p2s[t];
        q += g_p2q[t];
    }
    rs[tid] = s; rq[tid] = q;
    __syncthreads();
    for (int o = 128; o; o >>= 1) {
        if (tid < o) { rs[tid] += rs[tid+o]; rq[tid] += rq[tid+o]; }
        __syncthreads();
    }
    if (tid == 0) {
        double cnt = (double)BB * DD;
        double m = (double)rs[0]/cnt;
        double var = (double)rq[0]/cnt - m*m;
        float istd = (float)(1.0/sqrt(var + (double)EPS));
        float sc = istd * bn_gamma[0];
        s_ms[0] = sc;
        s_ms[1] = bn_beta[0] - (float)m * sc;
    }
    __syncthreads();
    int idx = blockIdx.x*256 + tid;
    out[(size_t)3*BB*DD + idx] = fmaf(g_y2[idx], s_ms[0], s_ms[1]);
}

extern "C" void kernel_launch(void* const* d_in, const int* in_sizes, int n_in,
                              void* d_out, int out_size)
{
    const int*   hrt      = (const int*)d_in[0];
    const int*   neb      = (const int*)d_in[1];
    const int*   nebr     = (const int*)d_in[2];
    const float* adj      = (const float*)d_in[3];
    const float* ent_W    = (const float*)d_in[4];
    const float* rel_W    = (const float*)d_in[5];
    const float* att_W    = (const float*)d_in[6];
    const float* att_b    = (const float*)d_in[7];
    const float* gcn_W    = (const float*)d_in[8];
    const float* gcn_b    = (const float*)d_in[9];
    const float* bn_gamma = (const float*)d_in[10];
    const float* bn_beta  = (const float*)d_in[11];
    float* out = (float*)d_out;

    cudaFuncSetAttribute(k1, cudaFuncAttributeMaxDynamicSharedMemorySize, SMEM_K1_BYTES);

    k0<<<16, 256>>>(att_W, gcn_W);
    k1<<<BB, 256, SMEM_K1_BYTES>>>(hrt, neb, nebr, adj, ent_W, rel_W,
                                   att_W, att_b, gcn_b, out);
    k2<<<NP1, 256>>>();
    k3<<<BB/2, 256>>>(adj, bn_gamma, bn_beta);
    k5<<<512, 256>>>(bn_gamma, bn_beta, out);
}

// round 17
// speedup vs baseline: 1.0718x; 1.0718x over previous
#include <cuda_runtime.h>
#include <math.h>

#define BB   1024
#define NN   50
#define NP1  51
#define DD   128
#define KK   8
#define EPS  1e-5f
#define ADJS 68                          // adjT row stride: gcd(68,32)=4 -> 4-way conflicts

typedef unsigned long long ull;

// ---- scratch (device globals) ----
__device__ float  g_y1[(size_t)BB * NP1 * DD];
__device__ float  g_y2[(size_t)BB * DD];
__device__ float  g_mean[NP1];
__device__ float  g_istd[NP1];
__device__ float  g_s1[(size_t)NP1 * BB];
__device__ float  g_s2[(size_t)NP1 * BB];
__device__ float  g_p2s[BB];
__device__ float  g_p2q[BB];
__device__ float4 g_Wp4[32 * 128];               // gcn_W packed [j4][d]
__device__ float4 g_Ap4[32 * 128];               // att_W packed [j4][d]

// ---- packed f32x2 helpers ----
#define FMA2(acc, a, b) asm("fma.rn.f32x2 %0, %1, %2, %0;" : "+l"(acc) : "l"(a), "l"(b))
__device__ __forceinline__ float2 unpk(ull v) {
    float2 r; asm("mov.b64 {%0,%1}, %2;" : "=f"(r.x), "=f"(r.y) : "l"(v)); return r;
}
__device__ __forceinline__ ull pk(float x, float y) {
    ull r; asm("mov.b64 %0, {%1,%2};" : "=l"(r) : "f"(x), "f"(y)); return r;
}

// ---- K1 smem layout (float offsets; vector regions 16B-aligned) ----
#define SM_X     0                       // [56][128]  x, later reused for xo
#define SM_ADJT  7168                    // [51][68]   adjT padded, i pad 51..67 = 0
#define SM_Q     10640                   // 128
#define SM_P     10768                   // 128
#define SM_ATT   10896                   // 64
#define SM_C     10960                   // 8
#define SM_RED   10968                   // 256
#define SM_NEB   11224                   // 52 ints
#define SM_NEBR  11276                   // 400 ints
#define SMEM_K1_FLOATS 11676
#define SMEM_K1_BYTES  (SMEM_K1_FLOATS * 4)   // ~45.6 KB

// k0: pack weight matrices into [j4][d] float4 layout
__global__ void k0(const float* __restrict__ att_W, const float* __restrict__ gcn_W)
{
    int idx = blockIdx.x * blockDim.x + threadIdx.x;
    if (idx < 32 * 128) {
        int j4 = idx >> 7, d = idx & 127;
        g_Wp4[idx] = *(const float4*)(gcn_W + (size_t)d * DD + 4 * j4);
        g_Ap4[idx] = *(const float4*)(att_W + (size_t)d * DD + 4 * j4);
    }
}

__global__ __launch_bounds__(256, 2) void k1(
    const int* __restrict__ hrt, const int* __restrict__ neb,
    const int* __restrict__ nebr, const float* __restrict__ adj,
    const float* __restrict__ ent_W, const float* __restrict__ rel_W,
    const float* __restrict__ att_W, const float* __restrict__ att_b,
    const float* __restrict__ gcn_b,
    float* __restrict__ out)
{
    extern __shared__ float sm[];
    const int b = blockIdx.x, tid = threadIdx.x;
    float* s_x    = sm + SM_X;
    float* s_adjT = sm + SM_ADJT;
    float* s_q    = sm + SM_Q;
    float* s_p    = sm + SM_P;
    float* s_att  = sm + SM_ATT;
    float* s_c    = sm + SM_C;
    float* s_red  = sm + SM_RED;
    int*   s_neb  = (int*)(sm + SM_NEB);
    int*   s_nebr = (int*)(sm + SM_NEBR);

    // ---- phase 1 (all threads): indices, sum_hrt, phantom-row zero (NO adjT) ----
    if (tid < DD) {
        int hi = hrt[3*b+0], ri = hrt[3*b+1], ti = hrt[3*b+2];
        float h = ent_W[(size_t)hi*DD + tid];
        float t = ent_W[(size_t)ti*DD + tid];
        float r = rel_W[(size_t)ri*DD + tid];
        out[(size_t)0*BB*DD + (size_t)b*DD + tid] = h;
        out[(size_t)1*BB*DD + (size_t)b*DD + tid] = t;
        out[(size_t)2*BB*DD + (size_t)b*DD + tid] = r;
        s_x[tid] = (h + t + r) * (1.0f/3.0f);
    }
    for (int t = tid; t < NN; t += 256) s_neb[t] = neb[b*NN + t];
    for (int t = tid; t < NN*KK; t += 256) s_nebr[t] = nebr[(size_t)b*NN*KK + t];
    // zero phantom rows 51..55 of s_x
    for (int idx = tid; idx < 5*DD; idx += 256) s_x[NP1*DD + idx] = 0.0f;
    __syncthreads();

    // ---- phase 2: warp-specialized ----
    if (tid < 128) {
        // warps 0-3: (b) gather subg rows 1..50
        const float4* ent4 = (const float4*)ent_W;
        const float4* rel4 = (const float4*)rel_W;
        for (int t = tid; t < NN*32; t += 128) {
            int n = t >> 5, c = t & 31;
            float4 e = ent4[(size_t)s_neb[n]*32 + c];
            const int* nr = s_nebr + n*KK;
            float4 rm = make_float4(0.f,0.f,0.f,0.f);
            #pragma unroll
            for (int k = 0; k < KK; k++) {
                float4 rv = rel4[(size_t)nr[k]*32 + c];
                rm.x += rv.x; rm.y += rv.y; rm.z += rv.z; rm.w += rv.w;
            }
            float4 o;
            o.x = 0.5f*(e.x + rm.x*0.125f);
            o.y = 0.5f*(e.y + rm.y*0.125f);
            o.z = 0.5f*(e.z + rm.z*0.125f);
            o.w = 0.5f*(e.w + rm.w*0.125f);
            *(float4*)(s_x + (n+1)*DD + 4*c) = o;
        }
    } else {
        // warps 4-7: (c) q[d] + c-partials; (d) p[j]; then adjT transpose (hidden under gather)
        const int d = tid - 128;
        {
            ull acc = 0;
            const ulonglong2* Ap = (const ulonglong2*)g_Ap4;
            #pragma unroll 8
            for (int j4 = 0; j4 < 32; j4++) {
                ulonglong2 w = Ap[j4*128 + d];
                ulonglong2 x = *(const ulonglong2*)(s_x + 4*j4);   // row 0 (phase 1)
                FMA2(acc, x.x, w.x);
                FMA2(acc, x.y, w.y);
            }
            float2 f = unpk(acc);
            float ab = att_b[d];
            float qv = f.x + f.y + ab;
            s_q[d] = qv;
            float cv = qv * ab;
            #pragma unroll
            for (int o = 16; o; o >>= 1) cv += __shfl_xor_sync(0xffffffffu, cv, o);
            if ((d & 31) == 0) s_c[1 + (d >> 5)] = cv;
        }
        asm volatile("bar.sync 1, 128;" ::: "memory");   // warps 4-7 only
        {
            float acc = 0.0f;
            #pragma unroll 8
            for (int dd = 0; dd < DD; dd++) acc = fmaf(s_q[dd], att_W[(size_t)dd*DD + d], acc);
            s_p[d] = acc;
            if (d == 0) s_c[0] = s_c[1] + s_c[2] + s_c[3] + s_c[4];
        }
        // adjT pad-zero + transpose, done by warps 4-7 while warps 0-3 still gathering
        for (int idx = d; idx < NP1*17; idx += 128) {
            int j = idx / 17, i = idx % 17;
            s_adjT[j*ADJS + NP1 + i] = 0.0f;
        }
        for (int idx = d; idx < NP1*NP1; idx += 128) {
            int i = idx / NP1, j = idx % NP1;
            s_adjT[j*ADJS + i] = adj[(size_t)b*NP1*NP1 + idx];
        }
    }
    __syncthreads();

    // (e) att[n] = leaky_relu( subg_n . p + c )
    {
        int warp = tid >> 5, lane = tid & 31;
        float c = s_c[0];
        for (int n = warp; n < NN; n += 8) {
            const float* row = s_x + (n+1)*DD;
            float v = 0.0f;
            #pragma unroll
            for (int k = 0; k < 4; k++) { int j = lane + 32*k; v = fmaf(row[j], s_p[j], v); }
            #pragma unroll
            for (int o = 16; o; o >>= 1) v += __shfl_xor_sync(0xffffffffu, v, o);
            if (lane == 0) {
                float a = v + c;
                s_att[n] = (a >= 0.0f) ? a : 0.01f*a;
            }
        }
    }
    __syncthreads();

    // (f) softmax over 50 (warp 0)
    if (tid < 32) {
        float v0 = (tid       < NN) ? s_att[tid]      : -3.4e38f;
        float v1 = (tid + 32  < NN) ? s_att[tid + 32] : -3.4e38f;
        float m = fmaxf(v0, v1);
        #pragma unroll
        for (int o = 16; o; o >>= 1) m = fmaxf(m, __shfl_xor_sync(0xffffffffu, m, o));
        float e0 = (tid      < NN) ? expf(v0 - m) : 0.0f;
        float e1 = (tid + 32 < NN) ? expf(v1 - m) : 0.0f;
        float s = e0 + e1;
        #pragma unroll
        for (int o = 16; o; o >>= 1) s += __shfl_xor_sync(0xffffffffu, s, o);
        float inv = 1.0f / s;
        if (tid      < NN) s_att[tid]      = e0*inv;
        if (tid + 32 < NN) s_att[tid + 32] = e1*inv;
    }
    __syncthreads();

    // (g) scale rows 1..50 in place
    for (int idx = tid; idx < NN*DD; idx += 256) s_x[DD + idx] *= s_att[idx >> 7];
    __syncthreads();

    // (h) xo[i][d] = gcn_b[d] + sum_j x[i][j]*gcn_W[d][j]
    // 2 d-cols x 14 rows per thread; results in regs, written back into s_x
    {
        const int d2 = tid & 63, rg = tid >> 6, i0 = rg * 14;
        ull acc[14][2];
        #pragma unroll
        for (int r = 0; r < 14; r++) { acc[r][0] = 0ULL; acc[r][1] = 0ULL; }
        const ulonglong2* Wp = (const ulonglong2*)g_Wp4;
        for (int j4 = 0; j4 < 32; j4++) {
            ulonglong2 w0 = Wp[j4*128 + 2*d2];
            ulonglong2 w1 = Wp[j4*128 + 2*d2 + 1];
            #pragma unroll
            for (int r = 0; r < 14; r++) {
                ulonglong2 xv = *(const ulonglong2*)(s_x + (i0+r)*DD + 4*j4);  // broadcast
                FMA2(acc[r][0], xv.x, w0.x); FMA2(acc[r][0], xv.y, w0.y);
                FMA2(acc[r][1], xv.x, w1.x); FMA2(acc[r][1], xv.y, w1.y);
            }
        }
        __syncthreads();   // all reads of s_x complete before overwrite
        float b0 = gcn_b[2*d2], b1 = gcn_b[2*d2+1];
        #pragma unroll
        for (int r = 0; r < 14; r++) {
            float2 f0 = unpk(acc[r][0]);
            float2 f1 = unpk(acc[r][1]);
            *(float2*)(s_x + (i0+r)*DD + 2*d2) =
                make_float2(f0.x + f0.y + b0, f1.x + f1.y + b1);
        }
    }
    __syncthreads();

    // (j) y1[i][d] = relu( sum_j adj[i][j]*xo[j][d] )   (xo lives in s_x)
    {
        const int d2 = tid & 63, rg = tid >> 6, i0 = rg * 16;
        const int lane = tid & 31, wh = (tid >> 5) & 1;
        ull acc[8][2];
        #pragma unroll
        for (int m = 0; m < 8; m++) { acc[m][0] = 0ULL; acc[m][1] = 0ULL; }
        #pragma unroll 3
        for (int j = 0; j < NP1; j++) {
            float2 xf = *(const float2*)(s_x + j*DD + 2*d2);
            ull x0 = pk(xf.x, xf.x), x1 = pk(xf.y, xf.y);
            const ulonglong2* ar = (const ulonglong2*)(s_adjT + j*ADJS + i0);  // broadcast
            #pragma unroll
            for (int q = 0; q < 4; q++) {
                ulonglong2 av = ar[q];
                FMA2(acc[2*q  ][0], av.x, x0); FMA2(acc[2*q  ][1], av.x, x1);
                FMA2(acc[2*q+1][0], av.y, x0); FMA2(acc[2*q+1][1], av.y, x1);
            }
        }
        #pragma unroll
        for (int m = 0; m < 8; m++) {
            float2 f0 = unpk(acc[m][0]);
            float2 f1 = unpk(acc[m][1]);
            float v00 = fmaxf(f0.x, 0.f), v01 = fmaxf(f1.x, 0.f);
            float v10 = fmaxf(f0.y, 0.f), v11 = fmaxf(f1.y, 0.f);
            int r0 = i0 + 2*m, r1 = r0 + 1;
            if (r0 < NP1) *(float2*)(g_y1 + ((size_t)b*NP1 + r0)*DD + 2*d2) = make_float2(v00, v01);
            if (r1 < NP1) *(float2*)(g_y1 + ((size_t)b*NP1 + r1)*DD + 2*d2) = make_float2(v10, v11);
            float sv0 = v00 + v01, sq0 = v00*v00 + v01*v01;
            float sv1 = v10 + v11, sq1 = v10*v10 + v11*v11;
            #pragma unroll
            for (int o = 16; o; o >>= 1) {
                sv0 += __shfl_xor_sync(0xffffffffu, sv0, o);
                sq0 += __shfl_xor_sync(0xffffffffu, sq0, o);
                sv1 += __shfl_xor_sync(0xffffffffu, sv1, o);
                sq1 += __shfl_xor_sync(0xffffffffu, sq1, o);
            }
            if (lane == 0) {
                if (r0 < NP1) { s_red[r0*2 + wh] = sv0; s_red[128 + r0*2 + wh] = sq0; }
                if (r1 < NP1) { s_red[r1*2 + wh] = sv1; s_red[128 + r1*2 + wh] = sq1; }
            }
        }
    }
    __syncthreads();
    if (tid < NP1) {
        g_s1[(size_t)tid*BB + b] = s_red[tid*2] + s_red[tid*2+1];
        g_s2[(size_t)tid*BB + b] = s_red[128 + tid*2] + s_red[128 + tid*2+1];
    }
}

// k2: reduce partials -> mean/istd  (fp32 fixed-order tree, fp64 finalize)
__global__ void k2(void)
{
    const int i = blockIdx.x, tid = threadIdx.x;
    float s = 0.0f, s2 = 0.0f;
    #pragma unroll
    for (int t = tid; t < BB; t += 256) {
        s  += g_s1[(size_t)i*BB + t];
        s2 += g_s2[(size_t)i*BB + t];
    }
    __shared__ float rs[256], rq[256];
    rs[tid] = s; rq[tid] = s2;
    __syncthreads();
    for (int o = 128; o; o >>= 1) {
        if (tid < o) { rs[tid] += rs[tid+o]; rq[tid] += rq[tid+o]; }
        __syncthreads();
    }
    if (tid == 0) {
        double cnt = (double)BB * DD;
        double m = (double)rs[0]/cnt;
        double var = (double)rq[0]/cnt - m*m;
        g_mean[i] = (float)m;
        g_istd[i] = (float)(1.0/sqrt(var + (double)EPS));
    }
}

// k3: y2 = relu( sum_j (a_j*sc_j)*y1_j + sum_j a_j*sh_j )  — BN folded, MLP-batched loads
__global__ __launch_bounds__(256) void k3(
    const float* __restrict__ adj,
    const float* __restrict__ bn_gamma, const float* __restrict__ bn_beta)
{
    __shared__ float4 s_part4[8 * 32];
    __shared__ float s_w[64];            // padded; rows 51..63 weight 0
    __shared__ float s_c0p[NP1];
    __shared__ float s_c0;
    __shared__ float s_r[8];
    const int b = blockIdx.x, tid = threadIdx.x;
    if (tid < 64) s_w[tid] = 0.0f;
    __syncthreads();
    if (tid < NP1) {
        float a  = adj[(size_t)b*NP1*NP1 + tid];     // adj row 0
        float sc = g_istd[tid] * bn_gamma[tid];
        float sh = bn_beta[tid] - g_mean[tid]*sc;
        s_w[tid]   = a * sc;
        s_c0p[tid] = a * sh;
    }
    __syncthreads();
    {
        const int d4 = tid & 31, jg = tid >> 5;
        const float* ybase = g_y1 + (size_t)b*NP1*DD + 4*d4;
        float4 v[7];
        float  w[7];
        #pragma unroll
        for (int t = 0; t < 7; t++) {
            int j = jg + 8*t;
            int jc = (j < NP1) ? j : NP1 - 1;
            w[t] = s_w[(j < 64) ? j : 63];
            if (j >= NP1) w[t] = 0.0f;
            v[t] = *(const float4*)(ybase + (size_t)jc*DD);
        }
        float4 acc = make_float4(0.f,0.f,0.f,0.f);
        #pragma unroll
        for (int t = 0; t < 7; t++) {
            acc.x = fmaf(w[t], v[t].x, acc.x); acc.y = fmaf(w[t], v[t].y, acc.y);
            acc.z = fmaf(w[t], v[t].z, acc.z); acc.w = fmaf(w[t], v[t].w, acc.w);
        }
        s_part4[jg*32 + d4] = acc;
    }
    if (tid < 32) {
        float v = s_c0p[tid] + ((tid + 32) < NP1 ? s_c0p[tid + 32] : 0.f);
        #pragma unroll
        for (int o = 16; o; o >>= 1) v += __shfl_xor_sync(0xffffffffu, v, o);
        if (tid == 0) s_c0 = v;
    }
    __syncthreads();
    if (tid < DD) {
        const float* s_part = (const float*)s_part4;
        float v = s_c0;
        #pragma unroll
        for (int g = 0; g < 8; g++) v += s_part[g*DD + tid];
        v = fmaxf(v, 0.f);
        g_y2[(size_t)b*DD + tid] = v;
        float sv = v, sq = v*v;
        #pragma unroll
        for (int o = 16; o; o >>= 1) {
            sv += __shfl_xor_sync(0xffffffffu, sv, o);
            sq += __shfl_xor_sync(0xffffffffu, sq, o);
        }
        if ((tid & 31) == 0) { s_r[tid>>5] = sv; s_r[4 + (tid>>5)] = sq; }
    }
    __syncthreads();
    if (tid == 0) {
        g_p2s[b] = s_r[0] + s_r[1] + s_r[2] + s_r[3];
        g_p2q[b] = s_r[4] + s_r[5] + s_r[6] + s_r[7];
    }
}

// k5: redundant deterministic reduce of BN2 partials (fp32 tree, fp64 finalize) + affine
__global__ __launch_bounds__(256) void k5(
    const float* __restrict__ bn_gamma, const float* __restrict__ bn_beta,
    float* __restrict__ out)
{
    __shared__ float rs[256], rq[256];
    __shared__ float s_ms[2];
    const int tid = threadIdx.x;
    float s = 0.0f, q = 0.0f;
    #pragma unroll
    for (int t = tid; t < BB; t += 256) {
        s += g_p2s[t];
        q += g_p2q[t];
    }
    rs[tid] = s; rq[tid] = q;
    __syncthreads();
    for (int o = 128; o; o >>= 1) {
        if (tid < o) { rs[tid] += rs[tid+o]; rq[tid] += rq[tid+o]; }
        __syncthreads();
    }
    if (tid == 0) {
        double cnt = (double)BB * DD;
        double m = (double)rs[0]/cnt;
        double var = (double)rq[0]/cnt - m*m;
        float istd = (float)(1.0/sqrt(var + (double)EPS));
        float sc = istd * bn_gamma[0];
        s_ms[0] = sc;
        s_ms[1] = bn_beta[0] - (float)m * sc;
    }
    __syncthreads();
    int idx = blockIdx.x*256 + tid;
    out[(size_t)3*BB*DD + idx] = fmaf(g_y2[idx], s_ms[0], s_ms[1]);
}

extern "C" void kernel_launch(void* const* d_in, const int* in_sizes, int n_in,
                              void* d_out, int out_size)
{
    const int*   hrt      = (const int*)d_in[0];
    const int*   neb      = (const int*)d_in[1];
    const int*   nebr     = (const int*)d_in[2];
    const float* adj      = (const float*)d_in[3];
    const float* ent_W    = (const float*)d_in[4];
    const float* rel_W    = (const float*)d_in[5];
    const float* att_W    = (const float*)d_in[6];
    const float* att_b    = (const float*)d_in[7];
    const float* gcn_W    = (const float*)d_in[8];
    const float* gcn_b    = (const float*)d_in[9];
    const float* bn_gamma = (const float*)d_in[10];
    const float* bn_beta  = (const float*)d_in[11];
    float* out = (float*)d_out;

    cudaFuncSetAttribute(k1, cudaFuncAttributeMaxDynamicSharedMemorySize, SMEM_K1_BYTES);

    k0<<<16, 256>>>(att_W, gcn_W);
    k1<<<BB, 256, SMEM_K1_BYTES>>>(hrt, neb, nebr, adj, ent_W, rel_W,
                                   att_W, att_b, gcn_b, out);
    k2<<<NP1, 256>>>();
    k3<<<BB, 256>>>(adj, bn_gamma, bn_beta);
    k5<<<512, 256>>>(bn_gamma, bn_beta, out);
}